// round 2
// baseline (speedup 1.0000x reference)
#include <cuda_runtime.h>
#include <math.h>

#define BATCH 16
#define NSZ 320
#define NPIX (320*320)
#define NPLANES (BATCH*2)
#define TOTAL (NPLANES*NPIX)
#define S320 0.055901699437494740f   /* 1/sqrt(320) */
#define COLSTRIDE 324

__device__ float g_z[TOTAL];
__device__ float g_x[TOTAL];
__device__ float g_t1[TOTAL];
__device__ float g_t2[TOTAL];
__device__ float g_xtv[TOTAL];
__device__ float2 g_tw[NSZ];

static __device__ __forceinline__ float2 cadd(float2 a, float2 b){ return make_float2(a.x+b.x, a.y+b.y); }
static __device__ __forceinline__ float2 csub(float2 a, float2 b){ return make_float2(a.x-b.x, a.y-b.y); }
static __device__ __forceinline__ float2 cmul(float2 a, float2 b){ return make_float2(a.x*b.x - a.y*b.y, a.x*b.y + a.y*b.x); }
static __device__ __forceinline__ float2 cmadd(float2 acc, float2 a, float2 b){
    acc.x += a.x*b.x - a.y*b.y;
    acc.y += a.x*b.y + a.y*b.x;
    return acc;
}

__global__ void init_tw_kernel()
{
    int j = threadIdx.x;
    double sv, cv;
    sincospi((double)j / 160.0, &sv, &cv);
    g_tw[j] = make_float2((float)cv, (float)(-sv));
}

// ---------------- Stockham stages for N=320 = 5*4*4*4 -------------------
// twiddle table tws[j] = exp(-2*pi*i*j/320); INV conjugates at use site.

template<int INV>
static __device__ __forceinline__ void stage5(const float2* __restrict__ src, float2* __restrict__ dst,
                                              const float2* __restrict__ tws, int u)
{
    // n=320, r=5, m=64, s=1, tmul=1 ; u in [0,64)
    float2 a0 = src[u], a1 = src[u+64], a2 = src[u+128], a3 = src[u+192], a4 = src[u+256];
    float2 w1 = tws[64], w2 = tws[128], w3 = tws[192], w4 = tws[256];
    if (INV){ w1.y=-w1.y; w2.y=-w2.y; w3.y=-w3.y; w4.y=-w4.y; }
    float2 b0 = cadd(cadd(a0,a1), cadd(cadd(a2,a3), a4));
    float2 b1 = a0; b1=cmadd(b1,a1,w1); b1=cmadd(b1,a2,w2); b1=cmadd(b1,a3,w3); b1=cmadd(b1,a4,w4);
    float2 b2 = a0; b2=cmadd(b2,a1,w2); b2=cmadd(b2,a2,w4); b2=cmadd(b2,a3,w1); b2=cmadd(b2,a4,w3);
    float2 b3 = a0; b3=cmadd(b3,a1,w3); b3=cmadd(b3,a2,w1); b3=cmadd(b3,a3,w4); b3=cmadd(b3,a4,w2);
    float2 b4 = a0; b4=cmadd(b4,a1,w4); b4=cmadd(b4,a2,w3); b4=cmadd(b4,a3,w2); b4=cmadd(b4,a4,w1);
    float2 t1 = tws[u], t2 = tws[2*u], t3 = tws[3*u], t4 = tws[4*u];
    if (INV){ t1.y=-t1.y; t2.y=-t2.y; t3.y=-t3.y; t4.y=-t4.y; }
    dst[5*u  ] = b0;
    dst[5*u+1] = cmul(b1,t1);
    dst[5*u+2] = cmul(b2,t2);
    dst[5*u+3] = cmul(b3,t3);
    dst[5*u+4] = cmul(b4,t4);
}

template<int M, int S, int TMUL, int INV>
static __device__ __forceinline__ void stage4(const float2* __restrict__ src, float2* __restrict__ dst,
                                              const float2* __restrict__ tws, int u)
{
    int p = u / S, q = u - p*S;
    float2 a0 = src[q + S*p];
    float2 a1 = src[q + S*(p +   M)];
    float2 a2 = src[q + S*(p + 2*M)];
    float2 a3 = src[q + S*(p + 3*M)];
    float2 s02 = cadd(a0,a2), d02 = csub(a0,a2);
    float2 s13 = cadd(a1,a3), d13 = csub(a1,a3);
    float2 jd  = INV ? make_float2(-d13.y, d13.x) : make_float2(d13.y, -d13.x); // (-i or +i)*d13
    float2 b0 = cadd(s02,s13);
    float2 b1 = cadd(d02,jd);
    float2 b2 = csub(s02,s13);
    float2 b3 = csub(d02,jd);
    float2 w1 = tws[TMUL*p], w2 = tws[2*TMUL*p], w3 = tws[3*TMUL*p];
    if (INV){ w1.y=-w1.y; w2.y=-w2.y; w3.y=-w3.y; }
    int base = q + S*4*p;
    dst[base      ] = b0;
    dst[base +   S] = cmul(b1,w1);
    dst[base + 2*S] = cmul(b2,w2);
    dst[base + 3*S] = cmul(b3,w3);
}

// ---------------- Row-pass FFT: 4 rows per block, 320 threads -----------
template<int INV, bool DUAL>
__global__ void __launch_bounds__(320) fft_row_kernel(const float* __restrict__ in,
                                                      float* __restrict__ o1,
                                                      float* __restrict__ o2)
{
    __shared__ float2 sA[4*320];
    __shared__ float2 sB[4*320];
    __shared__ float2 tws[320];
    int tid = threadIdx.x;
    tws[tid] = g_tw[tid];
    int b    = blockIdx.x / 80;
    int row0 = (blockIdx.x % 80) * 4;
    size_t base = (size_t)b*2*NPIX + (size_t)row0*NSZ;
    float sgn = (tid & 1) ? -1.f : 1.f;
    #pragma unroll
    for (int k = 0; k < 4; k++){
        float re = in[base + k*NSZ + tid];
        float im = in[base + NPIX + k*NSZ + tid];
        sA[k*NSZ + tid] = make_float2(re*sgn, im*sgn);
    }
    __syncthreads();
    int lr = tid / 80, u = tid % 80;
    float2* A  = sA + lr*NSZ;
    float2* Bp = sB + lr*NSZ;
    if (u < 64) stage5<INV>(A, Bp, tws, u);
    __syncthreads();
    stage4<16, 5, 5,INV>(Bp, A, tws, u);
    __syncthreads();
    stage4< 4,20,20,INV>(A, Bp, tws, u);
    __syncthreads();
    stage4< 1,80,80,INV>(Bp, A, tws, u);
    __syncthreads();
    float osg = sgn * S320;
    #pragma unroll
    for (int k = 0; k < 4; k++){
        float2 v = sA[k*NSZ + tid];
        o1[base + k*NSZ + tid]        = v.x*osg;
        o1[base + NPIX + k*NSZ + tid] = v.y*osg;
        if (DUAL){
            o2[base + k*NSZ + tid]        = v.x*osg;
            o2[base + NPIX + k*NSZ + tid] = v.y*osg;
        }
    }
}

// ------- Column-pass FFT: 8 columns/block, 640 threads.
// COMBINE: forward FFT -> k-space data consistency -> inverse FFT, all in smem.
template<int INV, bool COMBINE>
__global__ void __launch_bounds__(640) fft_col_kernel(const float* __restrict__ in,
                                                      const float* __restrict__ yk,
                                                      const float* __restrict__ mask,
                                                      float* __restrict__ out)
{
    __shared__ float2 sA[8*COLSTRIDE];
    __shared__ float2 sB[8*COLSTRIDE];
    __shared__ float2 tws[320];
    int tid = threadIdx.x;
    if (tid < 320) tws[tid] = g_tw[tid];
    int b    = blockIdx.x / 40;
    int col0 = (blockIdx.x % 40) * 8;
    size_t pb = (size_t)b*2*NPIX;
    #pragma unroll
    for (int k = 0; k < 4; k++){
        int e = tid + k*640;
        int row = e >> 3, c = e & 7;
        float s = (row & 1) ? -1.f : 1.f;
        float re = in[pb + (size_t)row*NSZ + col0 + c];
        float im = in[pb + NPIX + (size_t)row*NSZ + col0 + c];
        sA[c*COLSTRIDE + row] = make_float2(re*s, im*s);
    }
    __syncthreads();
    int cc = tid / 80, u = tid % 80;
    float2* A  = sA + cc*COLSTRIDE;
    float2* Bp = sB + cc*COLSTRIDE;
    if (COMBINE){
        if (u < 64) stage5<0>(A, Bp, tws, u);
        __syncthreads();
        stage4<16, 5, 5,0>(Bp, A, tws, u);  __syncthreads();
        stage4< 4,20,20,0>(A, Bp, tws, u);  __syncthreads();
        stage4< 1,80,80,0>(Bp, A, tws, u);  __syncthreads();
        // K' = K + m*(y-K) in true (centered, ortho) k-space coordinates
        #pragma unroll
        for (int k = 0; k < 4; k++){
            int e = tid + k*640;
            int row = e >> 3, c = e & 7;
            int idx = c*COLSTRIDE + row;
            float sg  = (row & 1) ? -S320 : S320;
            float2 K = sA[idx];
            K.x *= sg; K.y *= sg;
            float m  = mask[(size_t)b*NPIX + (size_t)row*NSZ + col0 + c];
            float yr = yk[pb + (size_t)row*NSZ + col0 + c];
            float yi = yk[pb + NPIX + (size_t)row*NSZ + col0 + c];
            K.x += m*(yr - K.x);
            K.y += m*(yi - K.y);
            float sg2 = (row & 1) ? -1.f : 1.f;   // pre-inverse centering sign
            sA[idx] = make_float2(K.x*sg2, K.y*sg2);
        }
        __syncthreads();
        if (u < 64) stage5<1>(A, Bp, tws, u);
        __syncthreads();
        stage4<16, 5, 5,1>(Bp, A, tws, u);  __syncthreads();
        stage4< 4,20,20,1>(A, Bp, tws, u);  __syncthreads();
        stage4< 1,80,80,1>(Bp, A, tws, u);  __syncthreads();
    } else {
        if (u < 64) stage5<INV>(A, Bp, tws, u);
        __syncthreads();
        stage4<16, 5, 5,INV>(Bp, A, tws, u);  __syncthreads();
        stage4< 4,20,20,INV>(A, Bp, tws, u);  __syncthreads();
        stage4< 1,80,80,INV>(Bp, A, tws, u);  __syncthreads();
    }
    #pragma unroll
    for (int k = 0; k < 4; k++){
        int e = tid + k*640;
        int row = e >> 3, c = e & 7;
        float s = (row & 1) ? -S320 : S320;
        float2 v = sA[c*COLSTRIDE + row];
        out[pb + (size_t)row*NSZ + col0 + c]        = v.x*s;
        out[pb + NPIX + (size_t)row*NSZ + col0 + c] = v.y*s;
    }
}

// ---------------- TV prox: whole 5-iter Chambolle per tile in smem ------
#define RG 44
#define RGS 45
__global__ void __launch_bounds__(256) tv_kernel(const float* __restrict__ in, float* __restrict__ outp)
{
    __shared__ float sxc[RG*RGS];
    __shared__ float spx[RG*RGS];
    __shared__ float spy[RG*RGS];
    __shared__ float su [RG*RGS];
    int pc  = blockIdx.z;
    int gx0 = blockIdx.x*32 - 6;
    int gy0 = blockIdx.y*32 - 6;
    size_t base = (size_t)pc * NPIX;
    for (int idx = threadIdx.x; idx < RG*RG; idx += 256){
        int ri = idx / RG, rj = idx - ri*RG;
        int gi = gy0 + ri, gj = gx0 + rj;
        float v = 0.f;
        if (gi >= 0 && gi < NSZ && gj >= 0 && gj < NSZ) v = in[base + gi*NSZ + gj];
        int o = ri*RGS + rj;
        sxc[o] = v; spx[o] = 0.f; spy[o] = 0.f;
    }
    __syncthreads();
    const float lam = 0.005f, tau = 0.25f;
    #pragma unroll 1
    for (int it = 0; it < 5; it++){
        for (int idx = threadIdx.x; idx < RG*RG; idx += 256){
            int ri = idx / RG, rj = idx - ri*RG;
            int gi = gy0 + ri, gj = gx0 + rj;
            int o = ri*RGS + rj;
            float pxc = spx[o], pyc = spy[o];
            float pxl = (rj > 0) ? spx[o-1]   : 0.f;
            float pyu = (ri > 0) ? spy[o-RGS] : 0.f;
            float dvx = (gj == 0) ? pxc : ((gj == NSZ-1) ? -pxl : pxc - pxl);
            float dvy = (gi == 0) ? pyc : ((gi == NSZ-1) ? -pyu : pyc - pyu);
            su[o] = sxc[o] - lam*(dvx + dvy);
        }
        __syncthreads();
        for (int idx = threadIdx.x; idx < RG*RG; idx += 256){
            int ri = idx / RG, rj = idx - ri*RG;
            int gi = gy0 + ri, gj = gx0 + rj;
            int o = ri*RGS + rj;
            float uc = su[o];
            float gx_ = 0.f, gy_ = 0.f;
            if (rj < RG-1 && gj < NSZ-1) gx_ = su[o+1]   - uc;
            if (ri < RG-1 && gi < NSZ-1) gy_ = su[o+RGS] - uc;
            float pnx = spx[o] + tau*gx_;
            float pny = spy[o] + tau*gy_;
            float nrm = sqrtf(fmaf(pnx,pnx, fmaf(pny,pny, 1e-8f)));
            float sc  = 1.f / fmaxf(nrm, 1.f);
            spx[o] = pnx*sc;
            spy[o] = pny*sc;
        }
        __syncthreads();
    }
    for (int idx = threadIdx.x; idx < 32*32; idx += 256){
        int ti = idx >> 5, tj = idx & 31;
        int ri = ti + 6, rj = tj + 6;
        int gi = gy0 + ri, gj = gx0 + rj;
        int o = ri*RGS + rj;
        float pxc = spx[o], pyc = spy[o];
        float pxl = spx[o-1], pyu = spy[o-RGS];
        float dvx = (gj == 0) ? pxc : ((gj == NSZ-1) ? -pxl : pxc - pxl);
        float dvy = (gi == 0) ? pyc : ((gi == NSZ-1) ? -pyu : pyc - pyu);
        outp[base + gi*NSZ + gj] = sxc[o] - lam*(dvx + dvy);
    }
}

// ------------- Wavelet: 3-level Haar + soft-threshold + momentum --------
#define IS2 0.70710678118654752f
static __device__ __forceinline__ float softf(float v){
    float m = fabsf(v) - 0.005f;
    m = fmaxf(m, 0.f);
    return copysignf(m, v);
}

template<int SS>
static __device__ __forceinline__ void dwt_level(float a[8][8]){
    float t[SS][SS];
    #pragma unroll
    for (int i = 0; i < SS; i++)
        #pragma unroll
        for (int j = 0; j < SS/2; j++){
            float e = a[i][2*j], o = a[i][2*j+1];
            t[i][j]      = (e+o)*IS2;
            t[i][j+SS/2] = (e-o)*IS2;
        }
    #pragma unroll
    for (int j = 0; j < SS; j++)
        #pragma unroll
        for (int i = 0; i < SS/2; i++){
            float e = t[2*i][j], o = t[2*i+1][j];
            a[i][j]      = (e+o)*IS2;
            a[i+SS/2][j] = (e-o)*IS2;
        }
    #pragma unroll
    for (int i = 0; i < SS; i++)
        #pragma unroll
        for (int j = 0; j < SS; j++)
            if (i >= SS/2 || j >= SS/2) a[i][j] = softf(a[i][j]);
}

template<int SS>
static __device__ __forceinline__ void idwt_level(float a[8][8]){
    float t[SS][SS];
    #pragma unroll
    for (int j = 0; j < SS; j++)
        #pragma unroll
        for (int i = 0; i < SS/2; i++){
            float e = a[i][j], o = a[i+SS/2][j];
            t[2*i][j]   = (e+o)*IS2;
            t[2*i+1][j] = (e-o)*IS2;
        }
    #pragma unroll
    for (int i = 0; i < SS; i++)
        #pragma unroll
        for (int j = 0; j < SS/2; j++){
            float e = t[i][j], o = t[i][j+SS/2];
            a[i][2*j]   = (e+o)*IS2;
            a[i][2*j+1] = (e-o)*IS2;
        }
}

__global__ void __launch_bounds__(256) wav_kernel(const float* __restrict__ xtv,
                                                  const float* __restrict__ xold,
                                                  float* __restrict__ xnew,
                                                  float* __restrict__ znew,
                                                  float beta)
{
    int t = blockIdx.x*256 + threadIdx.x;
    if (t >= NPLANES*40*40) return;
    int bx = t % 40;
    int tq = t / 40;
    int by = tq % 40;
    int pc = tq / 40;
    size_t base = (size_t)pc*NPIX + (size_t)by*8*NSZ + bx*8;
    float a[8][8];
    #pragma unroll
    for (int i = 0; i < 8; i++){
        float4 v0 = *reinterpret_cast<const float4*>(xtv + base + i*NSZ);
        float4 v1 = *reinterpret_cast<const float4*>(xtv + base + i*NSZ + 4);
        a[i][0]=v0.x; a[i][1]=v0.y; a[i][2]=v0.z; a[i][3]=v0.w;
        a[i][4]=v1.x; a[i][5]=v1.y; a[i][6]=v1.z; a[i][7]=v1.w;
    }
    dwt_level<8>(a); dwt_level<4>(a); dwt_level<2>(a);
    idwt_level<2>(a); idwt_level<4>(a); idwt_level<8>(a);
    #pragma unroll
    for (int i = 0; i < 8; i++){
        #pragma unroll
        for (int j = 0; j < 8; j++){
            float xn = a[i][j];
            float xo = xold[base + i*NSZ + j];
            xnew[base + i*NSZ + j] = xn;
            znew[base + i*NSZ + j] = xn + beta*(xn - xo);
        }
    }
}

// ----------------------------- host ------------------------------------
extern "C" void kernel_launch(void* const* d_in, const int* in_sizes, int n_in,
                              void* d_out, int out_size)
{
    const float* y    = (const float*)d_in[0];
    const float* mask = (const float*)d_in[1];
    float* out = (float*)d_out;
    float *z, *x, *t1, *t2, *xtv;
    cudaGetSymbolAddress((void**)&z,   g_z);
    cudaGetSymbolAddress((void**)&x,   g_x);
    cudaGetSymbolAddress((void**)&t1,  g_t1);
    cudaGetSymbolAddress((void**)&t2,  g_t2);
    cudaGetSymbolAddress((void**)&xtv, g_xtv);

    init_tw_kernel<<<1, 320>>>();

    // x0 = z0 = ifft2c(y)
    fft_col_kernel<1,false><<<BATCH*40, 640>>>(y, nullptr, nullptr, t1);
    fft_row_kernel<1,true ><<<BATCH*80, 320>>>(t1, x, z);

    double tt = 1.0;
    for (int it = 0; it < 15; it++){
        fft_row_kernel<0,false><<<BATCH*80, 320>>>(z, t1, nullptr);
        fft_col_kernel<0,true ><<<BATCH*40, 640>>>(t1, y, mask, t2);
        fft_row_kernel<1,false><<<BATCH*80, 320>>>(t2, t1, nullptr);
        tv_kernel<<<dim3(10,10,32), 256>>>(t1, xtv);
        double tn = 0.5*(1.0 + sqrt(1.0 + 4.0*tt*tt));
        float beta = (float)((tt - 1.0)/tn);
        float* xdst = (it == 14) ? out : x;
        wav_kernel<<<200, 256>>>(xtv, x, xdst, z, beta);
        tt = tn;
    }
}

// round 4
// speedup vs baseline: 1.0793x; 1.0793x over previous
#include <cuda_runtime.h>
#include <math.h>

#define BATCH 16
#define NSZ 320
#define NPIX (320*320)
#define NPLANES (BATCH*2)
#define TOTAL (NPLANES*NPIX)
#define S320 0.055901699437494740f   /* 1/sqrt(320) */
#define COLSTRIDE 324

__device__ float g_z[TOTAL];
__device__ float g_x[TOTAL];
__device__ float g_t1[TOTAL];
__device__ float g_t2[TOTAL];
__device__ float2 g_tw[NSZ];

static __device__ __forceinline__ float2 cadd(float2 a, float2 b){ return make_float2(a.x+b.x, a.y+b.y); }
static __device__ __forceinline__ float2 csub(float2 a, float2 b){ return make_float2(a.x-b.x, a.y-b.y); }
static __device__ __forceinline__ float2 cmul(float2 a, float2 b){ return make_float2(a.x*b.x - a.y*b.y, a.x*b.y + a.y*b.x); }
static __device__ __forceinline__ float2 cmadd(float2 acc, float2 a, float2 b){
    acc.x += a.x*b.x - a.y*b.y;
    acc.y += a.x*b.y + a.y*b.x;
    return acc;
}

__global__ void init_tw_kernel()
{
    int j = threadIdx.x;
    double sv, cv;
    sincospi((double)j / 160.0, &sv, &cv);
    g_tw[j] = make_float2((float)cv, (float)(-sv));
}

// ---------------- Stockham stages for N=320 = 5*4*4*4 -------------------
template<int INV>
static __device__ __forceinline__ void stage5(const float2* __restrict__ src, float2* __restrict__ dst,
                                              const float2* __restrict__ tws, int u)
{
    float2 a0 = src[u], a1 = src[u+64], a2 = src[u+128], a3 = src[u+192], a4 = src[u+256];
    float2 w1 = tws[64], w2 = tws[128], w3 = tws[192], w4 = tws[256];
    if (INV){ w1.y=-w1.y; w2.y=-w2.y; w3.y=-w3.y; w4.y=-w4.y; }
    float2 b0 = cadd(cadd(a0,a1), cadd(cadd(a2,a3), a4));
    float2 b1 = a0; b1=cmadd(b1,a1,w1); b1=cmadd(b1,a2,w2); b1=cmadd(b1,a3,w3); b1=cmadd(b1,a4,w4);
    float2 b2 = a0; b2=cmadd(b2,a1,w2); b2=cmadd(b2,a2,w4); b2=cmadd(b2,a3,w1); b2=cmadd(b2,a4,w3);
    float2 b3 = a0; b3=cmadd(b3,a1,w3); b3=cmadd(b3,a2,w1); b3=cmadd(b3,a3,w4); b3=cmadd(b3,a4,w2);
    float2 b4 = a0; b4=cmadd(b4,a1,w4); b4=cmadd(b4,a2,w3); b4=cmadd(b4,a3,w2); b4=cmadd(b4,a4,w1);
    float2 t1 = tws[u], t2 = tws[2*u], t3 = tws[3*u], t4 = tws[4*u];
    if (INV){ t1.y=-t1.y; t2.y=-t2.y; t3.y=-t3.y; t4.y=-t4.y; }
    dst[5*u  ] = b0;
    dst[5*u+1] = cmul(b1,t1);
    dst[5*u+2] = cmul(b2,t2);
    dst[5*u+3] = cmul(b3,t3);
    dst[5*u+4] = cmul(b4,t4);
}

template<int M, int S, int TMUL, int INV>
static __device__ __forceinline__ void stage4(const float2* __restrict__ src, float2* __restrict__ dst,
                                              const float2* __restrict__ tws, int u)
{
    int p = u / S, q = u - p*S;
    float2 a0 = src[q + S*p];
    float2 a1 = src[q + S*(p +   M)];
    float2 a2 = src[q + S*(p + 2*M)];
    float2 a3 = src[q + S*(p + 3*M)];
    float2 s02 = cadd(a0,a2), d02 = csub(a0,a2);
    float2 s13 = cadd(a1,a3), d13 = csub(a1,a3);
    float2 jd  = INV ? make_float2(-d13.y, d13.x) : make_float2(d13.y, -d13.x);
    float2 b0 = cadd(s02,s13);
    float2 b1 = cadd(d02,jd);
    float2 b2 = csub(s02,s13);
    float2 b3 = csub(d02,jd);
    float2 w1 = tws[TMUL*p], w2 = tws[2*TMUL*p], w3 = tws[3*TMUL*p];
    if (INV){ w1.y=-w1.y; w2.y=-w2.y; w3.y=-w3.y; }
    int base = q + S*4*p;
    dst[base      ] = b0;
    dst[base +   S] = cmul(b1,w1);
    dst[base + 2*S] = cmul(b2,w2);
    dst[base + 3*S] = cmul(b3,w3);
}

// ---------------- Row-pass FFT: 4 rows per block, 320 threads -----------
template<int INV, bool DUAL>
__global__ void __launch_bounds__(320) fft_row_kernel(const float* __restrict__ in,
                                                      float* __restrict__ o1,
                                                      float* __restrict__ o2)
{
    __shared__ float2 sA[4*320];
    __shared__ float2 sB[4*320];
    __shared__ float2 tws[320];
    int tid = threadIdx.x;
    tws[tid] = g_tw[tid];
    int b    = blockIdx.x / 80;
    int row0 = (blockIdx.x % 80) * 4;
    size_t base = (size_t)b*2*NPIX + (size_t)row0*NSZ;
    // vectorized load: thread -> (row k, 4-col group m)
    int k = tid / 80, m = tid % 80;
    {
        float4 vr = *reinterpret_cast<const float4*>(in + base + k*NSZ + 4*m);
        float4 vi = *reinterpret_cast<const float4*>(in + base + NPIX + k*NSZ + 4*m);
        float2* s = sA + k*NSZ + 4*m;
        s[0] = make_float2( vr.x,  vi.x);
        s[1] = make_float2(-vr.y, -vi.y);
        s[2] = make_float2( vr.z,  vi.z);
        s[3] = make_float2(-vr.w, -vi.w);
    }
    __syncthreads();
    int lr = tid / 80, u = tid % 80;
    float2* A  = sA + lr*NSZ;
    float2* Bp = sB + lr*NSZ;
    if (u < 64) stage5<INV>(A, Bp, tws, u);
    __syncthreads();
    stage4<16, 5, 5,INV>(Bp, A, tws, u);
    __syncthreads();
    stage4< 4,20,20,INV>(A, Bp, tws, u);
    __syncthreads();
    stage4< 1,80,80,INV>(Bp, A, tws, u);
    __syncthreads();
    {
        float2* s = sA + k*NSZ + 4*m;
        float2 v0 = s[0], v1 = s[1], v2 = s[2], v3 = s[3];
        float4 orr = make_float4( v0.x*S320, -v1.x*S320,  v2.x*S320, -v3.x*S320);
        float4 oii = make_float4( v0.y*S320, -v1.y*S320,  v2.y*S320, -v3.y*S320);
        *reinterpret_cast<float4*>(o1 + base + k*NSZ + 4*m)        = orr;
        *reinterpret_cast<float4*>(o1 + base + NPIX + k*NSZ + 4*m) = oii;
        if (DUAL){
            *reinterpret_cast<float4*>(o2 + base + k*NSZ + 4*m)        = orr;
            *reinterpret_cast<float4*>(o2 + base + NPIX + k*NSZ + 4*m) = oii;
        }
    }
}

// ------- Column-pass FFT: 8 columns/block, 640 threads.
// COMBINE: forward FFT -> k-space data consistency -> inverse FFT, all in smem.
template<int INV, bool COMBINE>
__global__ void __launch_bounds__(640) fft_col_kernel(const float* __restrict__ in,
                                                      const float* __restrict__ yk,
                                                      const float* __restrict__ mask,
                                                      float* __restrict__ out)
{
    __shared__ float2 sA[8*COLSTRIDE];
    __shared__ float2 sB[8*COLSTRIDE];
    __shared__ float2 tws[320];
    int tid = threadIdx.x;
    if (tid < 320) tws[tid] = g_tw[tid];
    int b    = blockIdx.x / 40;
    int col0 = (blockIdx.x % 40) * 8;
    size_t pb = (size_t)b*2*NPIX;
    int row = tid >> 1, half = tid & 1, cb = 4*half;
    float s0 = (row & 1) ? -1.f : 1.f;
    {
        float4 vr = *reinterpret_cast<const float4*>(in + pb + (size_t)row*NSZ + col0 + cb);
        float4 vi = *reinterpret_cast<const float4*>(in + pb + NPIX + (size_t)row*NSZ + col0 + cb);
        sA[(cb+0)*COLSTRIDE + row] = make_float2(vr.x*s0, vi.x*s0);
        sA[(cb+1)*COLSTRIDE + row] = make_float2(vr.y*s0, vi.y*s0);
        sA[(cb+2)*COLSTRIDE + row] = make_float2(vr.z*s0, vi.z*s0);
        sA[(cb+3)*COLSTRIDE + row] = make_float2(vr.w*s0, vi.w*s0);
    }
    __syncthreads();
    int cc = tid / 80, u = tid % 80;
    float2* A  = sA + cc*COLSTRIDE;
    float2* Bp = sB + cc*COLSTRIDE;
    if (COMBINE){
        if (u < 64) stage5<0>(A, Bp, tws, u);
        __syncthreads();
        stage4<16, 5, 5,0>(Bp, A, tws, u);  __syncthreads();
        stage4< 4,20,20,0>(A, Bp, tws, u);  __syncthreads();
        stage4< 1,80,80,0>(Bp, A, tws, u);  __syncthreads();
        // K' = K + m*(y-K) in true (centered, ortho) k-space coordinates
        {
            float sg  = s0 * S320;
            float4 mv = *reinterpret_cast<const float4*>(mask + (size_t)b*NPIX + (size_t)row*NSZ + col0 + cb);
            float4 yr = *reinterpret_cast<const float4*>(yk + pb + (size_t)row*NSZ + col0 + cb);
            float4 yi = *reinterpret_cast<const float4*>(yk + pb + NPIX + (size_t)row*NSZ + col0 + cb);
            float mm[4] = {mv.x, mv.y, mv.z, mv.w};
            float yrr[4] = {yr.x, yr.y, yr.z, yr.w};
            float yii[4] = {yi.x, yi.y, yi.z, yi.w};
            #pragma unroll
            for (int c = 0; c < 4; c++){
                int idx = (cb+c)*COLSTRIDE + row;
                float2 K = sA[idx];
                K.x *= sg; K.y *= sg;
                K.x += mm[c]*(yrr[c] - K.x);
                K.y += mm[c]*(yii[c] - K.y);
                sA[idx] = make_float2(K.x*s0, K.y*s0);
            }
        }
        __syncthreads();
        if (u < 64) stage5<1>(A, Bp, tws, u);
        __syncthreads();
        stage4<16, 5, 5,1>(Bp, A, tws, u);  __syncthreads();
        stage4< 4,20,20,1>(A, Bp, tws, u);  __syncthreads();
        stage4< 1,80,80,1>(Bp, A, tws, u);  __syncthreads();
    } else {
        if (u < 64) stage5<INV>(A, Bp, tws, u);
        __syncthreads();
        stage4<16, 5, 5,INV>(Bp, A, tws, u);  __syncthreads();
        stage4< 4,20,20,INV>(A, Bp, tws, u);  __syncthreads();
        stage4< 1,80,80,INV>(Bp, A, tws, u);  __syncthreads();
    }
    {
        float sg = s0 * S320;
        float2 v0 = sA[(cb+0)*COLSTRIDE + row];
        float2 v1 = sA[(cb+1)*COLSTRIDE + row];
        float2 v2 = sA[(cb+2)*COLSTRIDE + row];
        float2 v3 = sA[(cb+3)*COLSTRIDE + row];
        *reinterpret_cast<float4*>(out + pb + (size_t)row*NSZ + col0 + cb) =
            make_float4(v0.x*sg, v1.x*sg, v2.x*sg, v3.x*sg);
        *reinterpret_cast<float4*>(out + pb + NPIX + (size_t)row*NSZ + col0 + cb) =
            make_float4(v0.y*sg, v1.y*sg, v2.y*sg, v3.y*sg);
    }
}

// ----------- fused TV prox + 3-level Haar + threshold + momentum --------
#define RG 44
#define RGS 45
#define IS2 0.70710678118654752f
static __device__ __forceinline__ float softf(float v){
    float m = fabsf(v) - 0.005f;
    m = fmaxf(m, 0.f);
    return copysignf(m, v);
}

// forward Haar level on 32x33 smem tile (16 aligned 8x8 blocks), active 2H x 2H
template<int H>
static __device__ __forceinline__ void wav_fwd(float* __restrict__ sw, float* __restrict__ st, int tid)
{
    const int items = 16*2*H*H;
    for (int idx = tid; idx < items; idx += 256){
        int blk = idx / (2*H*H);
        int rem = idx - blk*(2*H*H);
        int r = rem / H;
        int j = rem - r*H;
        int rb = (blk>>2)*8 + r;
        int cb = (blk&3)*8;
        float e = sw[rb*33 + cb + 2*j];
        float o = sw[rb*33 + cb + 2*j + 1];
        st[rb*33 + cb + j]     = (e+o)*IS2;
        st[rb*33 + cb + H + j] = (e-o)*IS2;
    }
    __syncthreads();
    for (int idx = tid; idx < items; idx += 256){
        int blk = idx / (2*H*H);
        int rem = idx - blk*(2*H*H);
        int c = rem / H;
        int i = rem - c*H;
        int rb = (blk>>2)*8;
        int cb = (blk&3)*8;
        float e = st[(rb+2*i)*33 + cb + c];
        float o = st[(rb+2*i+1)*33 + cb + c];
        float lo = (e+o)*IS2, hi = (e-o)*IS2;
        sw[(rb+i)*33 + cb + c]   = (c < H) ? lo : softf(lo);
        sw[(rb+i+H)*33 + cb + c] = softf(hi);
    }
    __syncthreads();
}

template<int H>
static __device__ __forceinline__ void wav_inv(float* __restrict__ sw, float* __restrict__ st, int tid)
{
    const int items = 16*2*H*H;
    for (int idx = tid; idx < items; idx += 256){
        int blk = idx / (2*H*H);
        int rem = idx - blk*(2*H*H);
        int c = rem / H;
        int i = rem - c*H;
        int rb = (blk>>2)*8;
        int cb = (blk&3)*8;
        float a = sw[(rb+i)*33 + cb + c];
        float b = sw[(rb+i+H)*33 + cb + c];
        st[(rb+2*i)*33 + cb + c]   = (a+b)*IS2;
        st[(rb+2*i+1)*33 + cb + c] = (a-b)*IS2;
    }
    __syncthreads();
    for (int idx = tid; idx < items; idx += 256){
        int blk = idx / (2*H*H);
        int rem = idx - blk*(2*H*H);
        int r = rem / H;
        int j = rem - r*H;
        int rb = (blk>>2)*8;
        int cb = (blk&3)*8;
        float a = st[(rb+r)*33 + cb + j];
        float b = st[(rb+r)*33 + cb + j + H];
        sw[(rb+r)*33 + cb + 2*j]   = (a+b)*IS2;
        sw[(rb+r)*33 + cb + 2*j+1] = (a-b)*IS2;
    }
    __syncthreads();
}

__global__ void __launch_bounds__(256) tvwav_kernel(const float* __restrict__ in,
                                                    const float* __restrict__ xold,
                                                    float* __restrict__ xnew,
                                                    float* __restrict__ znew,
                                                    float beta)
{
    __shared__ float sxc[RG*RGS];
    __shared__ float spx[RG*RGS];
    __shared__ float spy[RG*RGS];
    __shared__ float su [RG*RGS];
    __shared__ float sw [32*33];
    __shared__ float st [32*33];
    int pc  = blockIdx.z;
    int gx0 = blockIdx.x*32 - 6;
    int gy0 = blockIdx.y*32 - 6;
    int tid = threadIdx.x;
    int base = pc * NPIX;
    for (int idx = tid; idx < RG*RG; idx += 256){
        int ri = idx / RG, rj = idx - ri*RG;
        int gi = gy0 + ri, gj = gx0 + rj;
        float v = 0.f;
        if (gi >= 0 && gi < NSZ && gj >= 0 && gj < NSZ) v = in[base + gi*NSZ + gj];
        int o = ri*RGS + rj;
        sxc[o] = v; su[o] = v; spx[o] = 0.f; spy[o] = 0.f;
    }
    __syncthreads();
    const float lam = 0.005f, tau = 0.25f;
    #pragma unroll 1
    for (int it = 0; it < 5; it++){
        if (it > 0){
            for (int idx = tid; idx < RG*RG; idx += 256){
                int ri = idx / RG, rj = idx - ri*RG;
                int gi = gy0 + ri, gj = gx0 + rj;
                int o = ri*RGS + rj;
                float pxc = spx[o], pyc = spy[o];
                float pxl = (rj > 0) ? spx[o-1]   : 0.f;
                float pyu = (ri > 0) ? spy[o-RGS] : 0.f;
                float dvx = (gj == 0) ? pxc : ((gj == NSZ-1) ? -pxl : pxc - pxl);
                float dvy = (gi == 0) ? pyc : ((gi == NSZ-1) ? -pyu : pyc - pyu);
                su[o] = sxc[o] - lam*(dvx + dvy);
            }
            __syncthreads();
        }
        for (int idx = tid; idx < RG*RG; idx += 256){
            int ri = idx / RG, rj = idx - ri*RG;
            int gi = gy0 + ri, gj = gx0 + rj;
            int o = ri*RGS + rj;
            float uc = su[o];
            float gx_ = 0.f, gy_ = 0.f;
            if (rj < RG-1 && gj < NSZ-1) gx_ = su[o+1]   - uc;
            if (ri < RG-1 && gi < NSZ-1) gy_ = su[o+RGS] - uc;
            float pnx = spx[o] + tau*gx_;
            float pny = spy[o] + tau*gy_;
            float s = fmaf(pnx,pnx, fmaf(pny,pny, 1e-8f));
            float sc = (s > 1.f) ? rsqrtf(s) : 1.f;
            spx[o] = pnx*sc;
            spy[o] = pny*sc;
        }
        __syncthreads();
    }
    // TV output for the inner 32x32 -> sw
    for (int idx = tid; idx < 32*32; idx += 256){
        int ti = idx >> 5, tj = idx & 31;
        int ri = ti + 6, rj = tj + 6;
        int gi = gy0 + ri, gj = gx0 + rj;
        int o = ri*RGS + rj;
        float pxc = spx[o], pyc = spy[o];
        float pxl = spx[o-1], pyu = spy[o-RGS];
        float dvx = (gj == 0) ? pxc : ((gj == NSZ-1) ? -pxl : pxc - pxl);
        float dvy = (gi == 0) ? pyc : ((gi == NSZ-1) ? -pyu : pyc - pyu);
        sw[ti*33 + tj] = sxc[o] - lam*(dvx + dvy);
    }
    __syncthreads();
    // 3-level Haar forward (+ soft threshold of details), then inverse
    wav_fwd<4>(sw, st, tid);
    wav_fwd<2>(sw, st, tid);
    wav_fwd<1>(sw, st, tid);
    wav_inv<1>(sw, st, tid);
    wav_inv<2>(sw, st, tid);
    wav_inv<4>(sw, st, tid);
    // momentum + store
    for (int idx = tid; idx < 32*32; idx += 256){
        int ti = idx >> 5, tj = idx & 31;
        int gi = gy0 + 6 + ti, gj = gx0 + 6 + tj;
        int g = base + gi*NSZ + gj;
        float xn = sw[ti*33 + tj];
        float xo = xold[g];
        xnew[g] = xn;
        znew[g] = xn + beta*(xn - xo);
    }
}

// ----------------------------- host ------------------------------------
extern "C" void kernel_launch(void* const* d_in, const int* in_sizes, int n_in,
                              void* d_out, int out_size)
{
    const float* y    = (const float*)d_in[0];
    const float* mask = (const float*)d_in[1];
    float* out = (float*)d_out;
    float *z, *x, *t1, *t2;
    cudaGetSymbolAddress((void**)&z,   g_z);
    cudaGetSymbolAddress((void**)&x,   g_x);
    cudaGetSymbolAddress((void**)&t1,  g_t1);
    cudaGetSymbolAddress((void**)&t2,  g_t2);

    init_tw_kernel<<<1, 320>>>();

    // x0 = z0 = ifft2c(y)
    fft_col_kernel<1,false><<<BATCH*40, 640>>>(y, nullptr, nullptr, t1);
    fft_row_kernel<1,true ><<<BATCH*80, 320>>>(t1, x, z);

    double tt = 1.0;
    for (int it = 0; it < 15; it++){
        fft_row_kernel<0,false><<<BATCH*80, 320>>>(z, t1, nullptr);
        fft_col_kernel<0,true ><<<BATCH*40, 640>>>(t1, y, mask, t2);
        fft_row_kernel<1,false><<<BATCH*80, 320>>>(t2, t1, nullptr);
        double tn = 0.5*(1.0 + sqrt(1.0 + 4.0*tt*tt));
        float beta = (float)((tt - 1.0)/tn);
        float* xdst = (it == 14) ? out : x;
        tvwav_kernel<<<dim3(10,10,32), 256>>>(t1, x, xdst, z, beta);
        tt = tn;
    }
}

// round 5
// speedup vs baseline: 1.5105x; 1.3996x over previous
#include <cuda_runtime.h>
#include <math.h>

#define BATCH 16
#define NSZ 320
#define NPIX (320*320)
#define NPLANES (BATCH*2)
#define TOTAL (NPLANES*NPIX)
#define S320 0.055901699437494740f   /* 1/sqrt(320) */
#define COLSTRIDE 324

__device__ float g_z[TOTAL];
__device__ float g_x[TOTAL];
__device__ float g_t1[TOTAL];
__device__ float g_t2[TOTAL];
__device__ float2 g_tw[NSZ];

static __device__ __forceinline__ float2 cadd(float2 a, float2 b){ return make_float2(a.x+b.x, a.y+b.y); }
static __device__ __forceinline__ float2 csub(float2 a, float2 b){ return make_float2(a.x-b.x, a.y-b.y); }
static __device__ __forceinline__ float2 cmul(float2 a, float2 b){ return make_float2(a.x*b.x - a.y*b.y, a.x*b.y + a.y*b.x); }
static __device__ __forceinline__ float2 cmadd(float2 acc, float2 a, float2 b){
    acc.x += a.x*b.x - a.y*b.y;
    acc.y += a.x*b.y + a.y*b.x;
    return acc;
}

__global__ void init_tw_kernel()
{
    int j = threadIdx.x;
    double sv, cv;
    sincospi((double)j / 160.0, &sv, &cv);
    g_tw[j] = make_float2((float)cv, (float)(-sv));
}

// ---------------- Stockham stages for N=320 = 5*4*4*4 -------------------
template<int INV>
static __device__ __forceinline__ void stage5(const float2* __restrict__ src, float2* __restrict__ dst,
                                              const float2* __restrict__ tws, int u)
{
    float2 a0 = src[u], a1 = src[u+64], a2 = src[u+128], a3 = src[u+192], a4 = src[u+256];
    float2 w1 = tws[64], w2 = tws[128], w3 = tws[192], w4 = tws[256];
    if (INV){ w1.y=-w1.y; w2.y=-w2.y; w3.y=-w3.y; w4.y=-w4.y; }
    float2 b0 = cadd(cadd(a0,a1), cadd(cadd(a2,a3), a4));
    float2 b1 = a0; b1=cmadd(b1,a1,w1); b1=cmadd(b1,a2,w2); b1=cmadd(b1,a3,w3); b1=cmadd(b1,a4,w4);
    float2 b2 = a0; b2=cmadd(b2,a1,w2); b2=cmadd(b2,a2,w4); b2=cmadd(b2,a3,w1); b2=cmadd(b2,a4,w3);
    float2 b3 = a0; b3=cmadd(b3,a1,w3); b3=cmadd(b3,a2,w1); b3=cmadd(b3,a3,w4); b3=cmadd(b3,a4,w2);
    float2 b4 = a0; b4=cmadd(b4,a1,w4); b4=cmadd(b4,a2,w3); b4=cmadd(b4,a3,w2); b4=cmadd(b4,a4,w1);
    float2 t1 = tws[u], t2 = tws[2*u], t3 = tws[3*u], t4 = tws[4*u];
    if (INV){ t1.y=-t1.y; t2.y=-t2.y; t3.y=-t3.y; t4.y=-t4.y; }
    dst[5*u  ] = b0;
    dst[5*u+1] = cmul(b1,t1);
    dst[5*u+2] = cmul(b2,t2);
    dst[5*u+3] = cmul(b3,t3);
    dst[5*u+4] = cmul(b4,t4);
}

template<int M, int S, int TMUL, int INV>
static __device__ __forceinline__ void stage4(const float2* __restrict__ src, float2* __restrict__ dst,
                                              const float2* __restrict__ tws, int u)
{
    int p = u / S, q = u - p*S;
    float2 a0 = src[q + S*p];
    float2 a1 = src[q + S*(p +   M)];
    float2 a2 = src[q + S*(p + 2*M)];
    float2 a3 = src[q + S*(p + 3*M)];
    float2 s02 = cadd(a0,a2), d02 = csub(a0,a2);
    float2 s13 = cadd(a1,a3), d13 = csub(a1,a3);
    float2 jd  = INV ? make_float2(-d13.y, d13.x) : make_float2(d13.y, -d13.x);
    float2 b0 = cadd(s02,s13);
    float2 b1 = cadd(d02,jd);
    float2 b2 = csub(s02,s13);
    float2 b3 = csub(d02,jd);
    float2 w1 = tws[TMUL*p], w2 = tws[2*TMUL*p], w3 = tws[3*TMUL*p];
    if (INV){ w1.y=-w1.y; w2.y=-w2.y; w3.y=-w3.y; }
    int base = q + S*4*p;
    dst[base      ] = b0;
    dst[base +   S] = cmul(b1,w1);
    dst[base + 2*S] = cmul(b2,w2);
    dst[base + 3*S] = cmul(b3,w3);
}

// ---------------- Row-pass FFT: 4 rows per block, 320 threads -----------
template<int INV, bool DUAL>
__global__ void __launch_bounds__(320) fft_row_kernel(const float* __restrict__ in,
                                                      float* __restrict__ o1,
                                                      float* __restrict__ o2)
{
    __shared__ float2 sA[4*320];
    __shared__ float2 sB[4*320];
    __shared__ float2 tws[320];
    int tid = threadIdx.x;
    tws[tid] = g_tw[tid];
    int b    = blockIdx.x / 80;
    int row0 = (blockIdx.x % 80) * 4;
    size_t base = (size_t)b*2*NPIX + (size_t)row0*NSZ;
    int k = tid / 80, m = tid % 80;
    {
        float4 vr = *reinterpret_cast<const float4*>(in + base + k*NSZ + 4*m);
        float4 vi = *reinterpret_cast<const float4*>(in + base + NPIX + k*NSZ + 4*m);
        float2* s = sA + k*NSZ + 4*m;
        s[0] = make_float2( vr.x,  vi.x);
        s[1] = make_float2(-vr.y, -vi.y);
        s[2] = make_float2( vr.z,  vi.z);
        s[3] = make_float2(-vr.w, -vi.w);
    }
    __syncthreads();
    int lr = tid / 80, u = tid % 80;
    float2* A  = sA + lr*NSZ;
    float2* Bp = sB + lr*NSZ;
    if (u < 64) stage5<INV>(A, Bp, tws, u);
    __syncthreads();
    stage4<16, 5, 5,INV>(Bp, A, tws, u);
    __syncthreads();
    stage4< 4,20,20,INV>(A, Bp, tws, u);
    __syncthreads();
    stage4< 1,80,80,INV>(Bp, A, tws, u);
    __syncthreads();
    {
        float2* s = sA + k*NSZ + 4*m;
        float2 v0 = s[0], v1 = s[1], v2 = s[2], v3 = s[3];
        float4 orr = make_float4( v0.x*S320, -v1.x*S320,  v2.x*S320, -v3.x*S320);
        float4 oii = make_float4( v0.y*S320, -v1.y*S320,  v2.y*S320, -v3.y*S320);
        *reinterpret_cast<float4*>(o1 + base + k*NSZ + 4*m)        = orr;
        *reinterpret_cast<float4*>(o1 + base + NPIX + k*NSZ + 4*m) = oii;
        if (DUAL){
            *reinterpret_cast<float4*>(o2 + base + k*NSZ + 4*m)        = orr;
            *reinterpret_cast<float4*>(o2 + base + NPIX + k*NSZ + 4*m) = oii;
        }
    }
}

// ------- Column-pass FFT: 8 columns/block, 640 threads.
template<int INV, bool COMBINE>
__global__ void __launch_bounds__(640) fft_col_kernel(const float* __restrict__ in,
                                                      const float* __restrict__ yk,
                                                      const float* __restrict__ mask,
                                                      float* __restrict__ out)
{
    __shared__ float2 sA[8*COLSTRIDE];
    __shared__ float2 sB[8*COLSTRIDE];
    __shared__ float2 tws[320];
    int tid = threadIdx.x;
    if (tid < 320) tws[tid] = g_tw[tid];
    int b    = blockIdx.x / 40;
    int col0 = (blockIdx.x % 40) * 8;
    size_t pb = (size_t)b*2*NPIX;
    int row = tid >> 1, half = tid & 1, cb = 4*half;
    float s0 = (row & 1) ? -1.f : 1.f;
    {
        float4 vr = *reinterpret_cast<const float4*>(in + pb + (size_t)row*NSZ + col0 + cb);
        float4 vi = *reinterpret_cast<const float4*>(in + pb + NPIX + (size_t)row*NSZ + col0 + cb);
        sA[(cb+0)*COLSTRIDE + row] = make_float2(vr.x*s0, vi.x*s0);
        sA[(cb+1)*COLSTRIDE + row] = make_float2(vr.y*s0, vi.y*s0);
        sA[(cb+2)*COLSTRIDE + row] = make_float2(vr.z*s0, vi.z*s0);
        sA[(cb+3)*COLSTRIDE + row] = make_float2(vr.w*s0, vi.w*s0);
    }
    __syncthreads();
    int cc = tid / 80, u = tid % 80;
    float2* A  = sA + cc*COLSTRIDE;
    float2* Bp = sB + cc*COLSTRIDE;
    if (COMBINE){
        if (u < 64) stage5<0>(A, Bp, tws, u);
        __syncthreads();
        stage4<16, 5, 5,0>(Bp, A, tws, u);  __syncthreads();
        stage4< 4,20,20,0>(A, Bp, tws, u);  __syncthreads();
        stage4< 1,80,80,0>(Bp, A, tws, u);  __syncthreads();
        {
            float sg  = s0 * S320;
            float4 mv = *reinterpret_cast<const float4*>(mask + (size_t)b*NPIX + (size_t)row*NSZ + col0 + cb);
            float4 yr = *reinterpret_cast<const float4*>(yk + pb + (size_t)row*NSZ + col0 + cb);
            float4 yi = *reinterpret_cast<const float4*>(yk + pb + NPIX + (size_t)row*NSZ + col0 + cb);
            float mm[4] = {mv.x, mv.y, mv.z, mv.w};
            float yrr[4] = {yr.x, yr.y, yr.z, yr.w};
            float yii[4] = {yi.x, yi.y, yi.z, yi.w};
            #pragma unroll
            for (int c = 0; c < 4; c++){
                int idx = (cb+c)*COLSTRIDE + row;
                float2 K = sA[idx];
                K.x *= sg; K.y *= sg;
                K.x += mm[c]*(yrr[c] - K.x);
                K.y += mm[c]*(yii[c] - K.y);
                sA[idx] = make_float2(K.x*s0, K.y*s0);
            }
        }
        __syncthreads();
        if (u < 64) stage5<1>(A, Bp, tws, u);
        __syncthreads();
        stage4<16, 5, 5,1>(Bp, A, tws, u);  __syncthreads();
        stage4< 4,20,20,1>(A, Bp, tws, u);  __syncthreads();
        stage4< 1,80,80,1>(Bp, A, tws, u);  __syncthreads();
    } else {
        if (u < 64) stage5<INV>(A, Bp, tws, u);
        __syncthreads();
        stage4<16, 5, 5,INV>(Bp, A, tws, u);  __syncthreads();
        stage4< 4,20,20,INV>(A, Bp, tws, u);  __syncthreads();
        stage4< 1,80,80,INV>(Bp, A, tws, u);  __syncthreads();
    }
    {
        float sg = s0 * S320;
        float2 v0 = sA[(cb+0)*COLSTRIDE + row];
        float2 v1 = sA[(cb+1)*COLSTRIDE + row];
        float2 v2 = sA[(cb+2)*COLSTRIDE + row];
        float2 v3 = sA[(cb+3)*COLSTRIDE + row];
        *reinterpret_cast<float4*>(out + pb + (size_t)row*NSZ + col0 + cb) =
            make_float4(v0.x*sg, v1.x*sg, v2.x*sg, v3.x*sg);
        *reinterpret_cast<float4*>(out + pb + NPIX + (size_t)row*NSZ + col0 + cb) =
            make_float4(v0.y*sg, v1.y*sg, v2.y*sg, v3.y*sg);
    }
}

// ----------- fused TV prox (register 2x2 patches) + Haar + momentum -----
// Tile: inner 32x32, halo 5 -> RG=42. 21x21 patches of 2x2, 441 active threads.
#define RG 42
#define IS2 0.70710678118654752f
static __device__ __forceinline__ float softf(float v){
    float m = fabsf(v) - 0.005f;
    m = fmaxf(m, 0.f);
    return copysignf(m, v);
}

template<int H, int NT>
static __device__ __forceinline__ void wav_fwd(float* __restrict__ sw, float* __restrict__ st, int tid)
{
    const int items = 16*2*H*H;
    for (int idx = tid; idx < items; idx += NT){
        int blk = idx / (2*H*H);
        int rem = idx - blk*(2*H*H);
        int r = rem / H;
        int j = rem - r*H;
        int rb = (blk>>2)*8 + r;
        int cb = (blk&3)*8;
        float e = sw[rb*33 + cb + 2*j];
        float o = sw[rb*33 + cb + 2*j + 1];
        st[rb*33 + cb + j]     = (e+o)*IS2;
        st[rb*33 + cb + H + j] = (e-o)*IS2;
    }
    __syncthreads();
    for (int idx = tid; idx < items; idx += NT){
        int blk = idx / (2*H*H);
        int rem = idx - blk*(2*H*H);
        int c = rem / H;
        int i = rem - c*H;
        int rb = (blk>>2)*8;
        int cb = (blk&3)*8;
        float e = st[(rb+2*i)*33 + cb + c];
        float o = st[(rb+2*i+1)*33 + cb + c];
        float lo = (e+o)*IS2, hi = (e-o)*IS2;
        sw[(rb+i)*33 + cb + c]   = (c < H) ? lo : softf(lo);
        sw[(rb+i+H)*33 + cb + c] = softf(hi);
    }
    __syncthreads();
}

template<int H, int NT>
static __device__ __forceinline__ void wav_inv(float* __restrict__ sw, float* __restrict__ st, int tid)
{
    const int items = 16*2*H*H;
    for (int idx = tid; idx < items; idx += NT){
        int blk = idx / (2*H*H);
        int rem = idx - blk*(2*H*H);
        int c = rem / H;
        int i = rem - c*H;
        int rb = (blk>>2)*8;
        int cb = (blk&3)*8;
        float a = sw[(rb+i)*33 + cb + c];
        float b = sw[(rb+i+H)*33 + cb + c];
        st[(rb+2*i)*33 + cb + c]   = (a+b)*IS2;
        st[(rb+2*i+1)*33 + cb + c] = (a-b)*IS2;
    }
    __syncthreads();
    for (int idx = tid; idx < items; idx += NT){
        int blk = idx / (2*H*H);
        int rem = idx - blk*(2*H*H);
        int r = rem / H;
        int j = rem - r*H;
        int rb = (blk>>2)*8;
        int cb = (blk&3)*8;
        float a = st[(rb+r)*33 + cb + j];
        float b = st[(rb+r)*33 + cb + j + H];
        sw[(rb+r)*33 + cb + 2*j]   = (a+b)*IS2;
        sw[(rb+r)*33 + cb + 2*j+1] = (a-b)*IS2;
    }
    __syncthreads();
}

__global__ void __launch_bounds__(448) tvwav_kernel(const float* __restrict__ in,
                                                    const float* __restrict__ xold,
                                                    float* __restrict__ xnew,
                                                    float* __restrict__ znew,
                                                    float beta)
{
    __shared__ float sUL [RG*21];   // u left-col of patch   [tile_row][patch_col]
    __shared__ float sUT [21*43];   // u top-row of patch    [patch_row][tile_col]
    __shared__ float sPxR[RG*21];   // px right-col of patch [tile_row][patch_col]
    __shared__ float sPyB[21*43];   // py bottom-row         [patch_row][tile_col]
    __shared__ float sw  [32*33];
    __shared__ float st  [32*33];

    int tid = threadIdx.x;
    bool act = tid < 441;
    int pr = tid / 21, pc = tid - pr*21;
    int ri = 2*pr, rj = 2*pc;
    int plane = blockIdx.z;
    int gx0 = blockIdx.x*32 - 5;
    int gy0 = blockIdx.y*32 - 5;
    int base = plane * NPIX;

    float x[2][2], u[2][2], px[2][2], py[2][2];
    bool jIs0[2], jIsN[2], iIs0[2], iIsN[2], gxOK[2], gyOK[2];

    if (act){
        #pragma unroll
        for (int i = 0; i < 2; i++){
            int gi = gy0 + ri + i;
            iIs0[i] = (gi == 0);
            iIsN[i] = (gi == NSZ-1);
            gyOK[i] = (ri + i < RG-1) && (gi < NSZ-1);
        }
        #pragma unroll
        for (int j = 0; j < 2; j++){
            int gj = gx0 + rj + j;
            jIs0[j] = (gj == 0);
            jIsN[j] = (gj == NSZ-1);
            gxOK[j] = (rj + j < RG-1) && (gj < NSZ-1);
        }
        #pragma unroll
        for (int i = 0; i < 2; i++){
            #pragma unroll
            for (int j = 0; j < 2; j++){
                int gi = gy0 + ri + i, gj = gx0 + rj + j;
                float v = 0.f;
                if (gi >= 0 && gi < NSZ && gj >= 0 && gj < NSZ) v = in[base + gi*NSZ + gj];
                x[i][j] = v; u[i][j] = v;
                px[i][j] = 0.f; py[i][j] = 0.f;
            }
        }
        sUL[ ri   *21 + pc] = u[0][0];
        sUL[(ri+1)*21 + pc] = u[1][0];
        sUT[pr*43 + rj    ] = u[0][0];
        sUT[pr*43 + rj + 1] = u[0][1];
    }
    __syncthreads();

    const float lam = 0.005f, tau = 0.25f;
    #pragma unroll 1
    for (int it = 0; it < 5; it++){
        if (act){
            // gather neighbor u (reads guarded: gxOK[1] implies pc<20, gyOK[1] implies pr<20)
            float uR0 = gxOK[1] ? sUL[ ri   *21 + pc + 1] : 0.f;
            float uR1 = gxOK[1] ? sUL[(ri+1)*21 + pc + 1] : 0.f;
            float uD0 = gyOK[1] ? sUT[(pr+1)*43 + rj    ] : 0.f;
            float uD1 = gyOK[1] ? sUT[(pr+1)*43 + rj + 1] : 0.f;
            #pragma unroll
            for (int i = 0; i < 2; i++){
                #pragma unroll
                for (int j = 0; j < 2; j++){
                    float gx = 0.f, gy = 0.f;
                    if (gxOK[j]) gx = ((j == 0) ? u[i][1] : ((i == 0) ? uR0 : uR1)) - u[i][j];
                    if (gyOK[i]) gy = ((i == 0) ? u[1][j] : ((j == 0) ? uD0 : uD1)) - u[i][j];
                    float pnx = fmaf(tau, gx, px[i][j]);
                    float pny = fmaf(tau, gy, py[i][j]);
                    float s  = fmaf(pnx, pnx, fmaf(pny, pny, 1e-8f));
                    float sc = (s > 1.f) ? rsqrtf(s) : 1.f;
                    px[i][j] = pnx*sc;
                    py[i][j] = pny*sc;
                }
            }
            sPxR[ ri   *21 + pc] = px[0][1];
            sPxR[(ri+1)*21 + pc] = px[1][1];
            sPyB[pr*43 + rj    ] = py[1][0];
            sPyB[pr*43 + rj + 1] = py[1][1];
        }
        __syncthreads();
        if (act){
            float pxL0 = (pc > 0) ? sPxR[ ri   *21 + pc - 1] : 0.f;
            float pxL1 = (pc > 0) ? sPxR[(ri+1)*21 + pc - 1] : 0.f;
            float pyU0 = (pr > 0) ? sPyB[(pr-1)*43 + rj    ] : 0.f;
            float pyU1 = (pr > 0) ? sPyB[(pr-1)*43 + rj + 1] : 0.f;
            #pragma unroll
            for (int i = 0; i < 2; i++){
                #pragma unroll
                for (int j = 0; j < 2; j++){
                    float pxl = (j == 1) ? px[i][0] : ((i == 0) ? pxL0 : pxL1);
                    float pyu = (i == 1) ? py[0][j] : ((j == 0) ? pyU0 : pyU1);
                    float dvx = jIs0[j] ? px[i][j] : (jIsN[j] ? -pxl : px[i][j] - pxl);
                    float dvy = iIs0[i] ? py[i][j] : (iIsN[i] ? -pyu : py[i][j] - pyu);
                    u[i][j] = x[i][j] - lam*(dvx + dvy);
                }
            }
        }
        if (it < 4){
            if (act){
                sUL[ ri   *21 + pc] = u[0][0];
                sUL[(ri+1)*21 + pc] = u[1][0];
                sUT[pr*43 + rj    ] = u[0][0];
                sUT[pr*43 + rj + 1] = u[0][1];
            }
            __syncthreads();
        }
    }

    // deposit inner 32x32 TV output into sw
    if (act){
        #pragma unroll
        for (int i = 0; i < 2; i++){
            #pragma unroll
            for (int j = 0; j < 2; j++){
                int ti = ri + i - 5, tj = rj + j - 5;
                if (ti >= 0 && ti < 32 && tj >= 0 && tj < 32)
                    sw[ti*33 + tj] = u[i][j];
            }
        }
    }
    __syncthreads();

    // 3-level Haar forward (+ soft threshold), then inverse
    wav_fwd<4,448>(sw, st, tid);
    wav_fwd<2,448>(sw, st, tid);
    wav_fwd<1,448>(sw, st, tid);
    wav_inv<1,448>(sw, st, tid);
    wav_inv<2,448>(sw, st, tid);
    wav_inv<4,448>(sw, st, tid);

    // momentum + store
    for (int idx = tid; idx < 32*32; idx += 448){
        int ti = idx >> 5, tj = idx & 31;
        int gi = gy0 + 5 + ti, gj = gx0 + 5 + tj;
        int g = base + gi*NSZ + gj;
        float xn = sw[ti*33 + tj];
        float xo = xold[g];
        xnew[g] = xn;
        znew[g] = xn + beta*(xn - xo);
    }
}

// ----------------------------- host ------------------------------------
extern "C" void kernel_launch(void* const* d_in, const int* in_sizes, int n_in,
                              void* d_out, int out_size)
{
    const float* y    = (const float*)d_in[0];
    const float* mask = (const float*)d_in[1];
    float* out = (float*)d_out;
    float *z, *x, *t1, *t2;
    cudaGetSymbolAddress((void**)&z,   g_z);
    cudaGetSymbolAddress((void**)&x,   g_x);
    cudaGetSymbolAddress((void**)&t1,  g_t1);
    cudaGetSymbolAddress((void**)&t2,  g_t2);

    init_tw_kernel<<<1, 320>>>();

    // x0 = z0 = ifft2c(y)
    fft_col_kernel<1,false><<<BATCH*40, 640>>>(y, nullptr, nullptr, t1);
    fft_row_kernel<1,true ><<<BATCH*80, 320>>>(t1, x, z);

    double tt = 1.0;
    for (int it = 0; it < 15; it++){
        fft_row_kernel<0,false><<<BATCH*80, 320>>>(z, t1, nullptr);
        fft_col_kernel<0,true ><<<BATCH*40, 640>>>(t1, y, mask, t2);
        fft_row_kernel<1,false><<<BATCH*80, 320>>>(t2, t1, nullptr);
        double tn = 0.5*(1.0 + sqrt(1.0 + 4.0*tt*tt));
        float beta = (float)((tt - 1.0)/tn);
        float* xdst = (it == 14) ? out : x;
        tvwav_kernel<<<dim3(10,10,32), 448>>>(t1, x, xdst, z, beta);
        tt = tn;
    }
}